// round 16
// baseline (speedup 1.0000x reference)
#include <cuda_runtime.h>
#include <cuda_bf16.h>
#include <cstdint>

#define GLYPH_DIM 4096
#define PAD_IDX   4096
#define EMB_DIM   20
#define HIDDEN    32
#define MAX_LEN   64
#define HW        1659        // 21 * 79
#define WPB       8           // warps per block
#define SPW       2           // samples per warp
#define WIN       1024        // presence window size
#define NPROD     128         // producer blocks for utab

typedef unsigned long long ull;

// ---------------------------------------------------------------------------
// Device scratch
// ---------------------------------------------------------------------------
__device__ float g_utab[(GLYPH_DIM + 1) * HIDDEN];
__device__ ull   g_done;      // monotonic producer counter (zero at module load)

// ---------------------------------------------------------------------------
// Mega kernel
// ---------------------------------------------------------------------------
__global__ __launch_bounds__(WPB * 32, 3) void mega_kernel(
    const int* __restrict__ chars,
    const int* __restrict__ colors,
    const float* __restrict__ emb,
    const float* __restrict__ W_ih,
    const float* __restrict__ W_hh,
    const float* __restrict__ b_ih,
    const float* __restrict__ b_hh,
    float* __restrict__ out_h,
    float* __restrict__ out_emb,
    float* __restrict__ out_bag,
    int B)
{
    __shared__ __align__(16) unsigned char presence[WPB][WIN];       // 8 KB
    __shared__ __align__(16) int   bagsh[WPB][SPW][MAX_LEN + 4];
    __shared__ __align__(16) float hsm  [WPB][SPW][2][HIDDEN];

    const int lane = threadIdx.x & 31;
    const int w    = threadIdx.x >> 5;

    // ---- utab producer prologue (blocks 0..NPROD-1) ----
    if (blockIdx.x < NPROD) {
        const int uw = blockIdx.x * WPB + w;          // 0..1023
        const float4* wr = (const float4*)(W_ih + lane * EMB_DIM);
        float4 w0 = __ldg(&wr[0]), w1 = __ldg(&wr[1]), w2 = __ldg(&wr[2]),
               w3 = __ldg(&wr[3]), w4 = __ldg(&wr[4]);
        float bias = __ldg(&b_ih[lane]) + __ldg(&b_hh[lane]);
        for (int row = uw; row <= GLYPH_DIM; row += NPROD * WPB) {
            const float4* er = (const float4*)(emb + (size_t)row * EMB_DIM);
            float4 e0 = __ldg(&er[0]), e1 = __ldg(&er[1]), e2 = __ldg(&er[2]),
                   e3 = __ldg(&er[3]), e4 = __ldg(&er[4]);
            float acc = bias;
            acc += w0.x*e0.x + w0.y*e0.y + w0.z*e0.z + w0.w*e0.w;
            acc += w1.x*e1.x + w1.y*e1.y + w1.z*e1.z + w1.w*e1.w;
            acc += w2.x*e2.x + w2.y*e2.y + w2.z*e2.z + w2.w*e2.w;
            acc += w3.x*e3.x + w3.y*e3.y + w3.z*e3.z + w3.w*e3.w;
            acc += w4.x*e4.x + w4.y*e4.y + w4.z*e4.z + w4.w*e4.w;
            g_utab[row * HIDDEN + lane] = acc;
        }
        __syncthreads();
        if (threadIdx.x == 0) {
            __threadfence();
            atomicAdd(&g_done, 1ull);
        }
    }

    const int gw = blockIdx.x * WPB + w;              // global warp id
    const int samp0 = gw * SPW;
    if (samp0 >= B) return;

    int steps_arr[SPW];

    // ---- bag construction + outputs, per sample (sequential) ----
    for (int s = 0; s < SPW; s++) {
        const int sample = samp0 + s;
        if (sample >= B) {
            steps_arr[s] = 0;
#pragma unroll
            for (int i = lane; i < MAX_LEN; i += 32) bagsh[w][s][i] = PAD_IDX;
            __syncwarp();
            continue;
        }

        const size_t base = (size_t)sample * HW;
        const int* cp = chars + base;
        const int* kp = colors + base;
        const int mis = (int)(base & 3);
        const int pre = (4 - mis) & 3;
        const int nv  = (HW - pre) >> 2;
        const int rem = HW - pre - (nv << 2);
        const int4* cp4 = (const int4*)(cp + pre);
        const int4* kp4 = (const int4*)(kp + pre);

        int o_acc = 0;
        for (int wnd = 0; wnd < GLYPH_DIM / WIN; wnd++) {
            const int wb = wnd << 10;

            {
                uint4 z = make_uint4(0u, 0u, 0u, 0u);
                uint4* p4 = (uint4*)presence[w];
                p4[lane] = z;
                p4[lane + 32] = z;
            }
            __syncwarp();

            if (lane < pre) {
                unsigned rel = (unsigned)((__ldg(&cp[lane]) << 4) + __ldg(&kp[lane]) - wb);
                if (rel < WIN) presence[w][rel] = 1;
            }
#pragma unroll 4
            for (int i = lane; i < nv; i += 32) {
                int4 c = __ldg(&cp4[i]);
                int4 k = __ldg(&kp4[i]);
                unsigned r0 = (unsigned)((c.x << 4) + k.x - wb);
                unsigned r1 = (unsigned)((c.y << 4) + k.y - wb);
                unsigned r2 = (unsigned)((c.z << 4) + k.z - wb);
                unsigned r3 = (unsigned)((c.w << 4) + k.w - wb);
                if (r0 < WIN) presence[w][r0] = 1;
                if (r1 < WIN) presence[w][r1] = 1;
                if (r2 < WIN) presence[w][r2] = 1;
                if (r3 < WIN) presence[w][r3] = 1;
            }
            if (lane < rem) {
                int idx = pre + (nv << 2) + lane;
                unsigned rel = (unsigned)((__ldg(&cp[idx]) << 4) + __ldg(&kp[idx]) - wb);
                if (rel < WIN) presence[w][rel] = 1;
            }
            __syncwarp();

            unsigned combined;
            {
                const uint4* pq = (const uint4*)presence[w];
                uint4 A  = pq[lane];
                uint4 Bv = pq[lane + 32];
                unsigned lo = (((A.x  * 0x01020408u) >> 24) & 0xFu)
                            | ((((A.y  * 0x01020408u) >> 24) & 0xFu) << 4)
                            | ((((A.z  * 0x01020408u) >> 24) & 0xFu) << 8)
                            | ((((A.w  * 0x01020408u) >> 24) & 0xFu) << 12);
                unsigned hi = (((Bv.x * 0x01020408u) >> 24) & 0xFu)
                            | ((((Bv.y * 0x01020408u) >> 24) & 0xFu) << 4)
                            | ((((Bv.z * 0x01020408u) >> 24) & 0xFu) << 8)
                            | ((((Bv.w * 0x01020408u) >> 24) & 0xFu) << 12);
                combined = lo | (hi << 16);
            }
            unsigned v0 = __shfl_sync(0xffffffffu, combined, (2 * lane) & 31);
            unsigned v1 = __shfl_sync(0xffffffffu, combined, (2 * lane + 1) & 31);
            if (lane >= 16) { v0 >>= 16; v1 >>= 16; }
            unsigned word = (v0 & 0xFFFFu) | ((v1 & 0xFFFFu) << 16);

            int cnt = __popc(word);
            int incl = cnt;
#pragma unroll
            for (int d = 1; d < 32; d <<= 1) {
                int n = __shfl_up_sync(0xffffffffu, incl, d);
                if (lane >= d) incl += n;
            }
            int wtotal = __shfl_sync(0xffffffffu, incl, 31);
            int o = o_acc + incl - cnt;

            unsigned mm = word;
            int idbase = wb + 32 * lane;
            while (mm && o < MAX_LEN) {
                int b = __ffs(mm) - 1;
                bagsh[w][s][o++] = idbase + b;
                mm &= mm - 1;
            }
            o_acc += wtotal;
            __syncwarp();
            if (o_acc >= MAX_LEN) break;
        }

        steps_arr[s] = o_acc < MAX_LEN ? o_acc : MAX_LEN;
#pragma unroll
        for (int i = lane; i < MAX_LEN; i += 32)
            if (i >= o_acc) bagsh[w][s][i] = PAD_IDX;
        __syncwarp();

        // bag output
        if (lane < 16) {
            int4 bi = ((const int4*)bagsh[w][s])[lane];
            float4 bf;
            bf.x = (float)bi.x; bf.y = (float)bi.y;
            bf.z = (float)bi.z; bf.w = (float)bi.w;
            ((float4*)(out_bag + (size_t)sample * MAX_LEN))[lane] = bf;
        }
        // emb gather
        {
            float4* dst4 = (float4*)(out_emb + (size_t)sample * (MAX_LEN * EMB_DIM));
            const float4* esrc = (const float4*)emb;
#pragma unroll
            for (int it = 0; it < 10; it++) {
                int e4 = it * 32 + lane;
                int r  = e4 / 5;
                int k  = e4 - r * 5;
                int g  = bagsh[w][s][r];
                dst4[e4] = __ldg(&esrc[(size_t)g * 5 + k]);
            }
        }
    }

    // ---- wait for utab ----
    if (lane == 0) {
        volatile ull* dp = &g_done;
        while (*dp < (ull)NPROD) { __nanosleep(64); }
    }
    __syncwarp();
    __threadfence();

    // ---- RNN: quarter-j split, scalar-collapse, TWO samples interleaved ----
    const int jq = lane >> 3;
    const int p  = lane & 7;
    const int myrow = 4 * p + 2 * (jq & 1) + (jq >> 1);
    const bool keep_lo1 = (jq & 1) == 0;
    const bool keep_lo2 = (jq >> 1) == 0;

    ull wreg[4][4];                      // shared across both samples
    {
#pragma unroll
        for (int r = 0; r < 4; r++) {
            const ull* wp = (const ull*)(W_hh + (4 * p + r) * HIDDEN + 8 * jq);
#pragma unroll
            for (int k = 0; k < 4; k++) wreg[r][k] = __ldg(&wp[k]);
        }
    }

    int idA0 = bagsh[w][0][lane];
    int idA1 = bagsh[w][0][32 + lane];
    int idB0 = bagsh[w][1][lane];
    int idB1 = bagsh[w][1][32 + lane];
    const int stepsA = steps_arr[0];
    const int stepsB = steps_arr[1];

    hsm[w][0][0][lane] = 0.f;
    hsm[w][1][0][lane] = 0.f;
    float hA = 0.f, hB = 0.f;
    int buf = 0;
    __syncwarp();

    float uringA[4], uringB[4];
#pragma unroll
    for (int k = 0; k < 4; k++) {
        int gA = __shfl_sync(0xffffffffu, idA0, k);
        int gB = __shfl_sync(0xffffffffu, idB0, k);
        uringA[k] = __ldg(&g_utab[gA * HIDDEN + myrow]);
        uringB[k] = __ldg(&g_utab[gB * HIDDEN + myrow]);
    }

#pragma unroll 2
    for (int t = 0; t < MAX_LEN; t++) {
        float uA = uringA[t & 3];
        float uB = uringB[t & 3];
        {
            int tn = t + 4;
            if (tn > MAX_LEN - 1) tn = MAX_LEN - 1;
            int gA = __shfl_sync(0xffffffffu, (tn < 32) ? idA0 : idA1, tn & 31);
            int gB = __shfl_sync(0xffffffffu, (tn < 32) ? idB0 : idB1, tn & 31);
            uringA[t & 3] = __ldg(&g_utab[gA * HIDDEN + myrow]);
            uringB[t & 3] = __ldg(&g_utab[gB * HIDDEN + myrow]);
        }

        const ulonglong2* hpA = (const ulonglong2*)&hsm[w][0][buf][8 * jq];
        const ulonglong2* hpB = (const ulonglong2*)&hsm[w][1][buf][8 * jq];
        ulonglong2 qA0 = hpA[0];
        ulonglong2 qA1 = hpA[1];
        ulonglong2 qB0 = hpB[0];
        ulonglong2 qB1 = hpB[1];

        ull aA0 = 0ull, aA1 = 0ull, aA2 = 0ull, aA3 = 0ull;
        ull aB0 = 0ull, aB1 = 0ull, aB2 = 0ull, aB3 = 0ull;
#pragma unroll
        for (int k = 0; k < 4; k++) {
            ull qa = (k == 0) ? qA0.x : (k == 1) ? qA0.y : (k == 2) ? qA1.x : qA1.y;
            ull qb = (k == 0) ? qB0.x : (k == 1) ? qB0.y : (k == 2) ? qB1.x : qB1.y;
            asm("fma.rn.f32x2 %0, %1, %2, %3;" : "=l"(aA0) : "l"(wreg[0][k]), "l"(qa), "l"(aA0));
            asm("fma.rn.f32x2 %0, %1, %2, %3;" : "=l"(aB0) : "l"(wreg[0][k]), "l"(qb), "l"(aB0));
            asm("fma.rn.f32x2 %0, %1, %2, %3;" : "=l"(aA1) : "l"(wreg[1][k]), "l"(qa), "l"(aA1));
            asm("fma.rn.f32x2 %0, %1, %2, %3;" : "=l"(aB1) : "l"(wreg[1][k]), "l"(qb), "l"(aB1));
            asm("fma.rn.f32x2 %0, %1, %2, %3;" : "=l"(aA2) : "l"(wreg[2][k]), "l"(qa), "l"(aA2));
            asm("fma.rn.f32x2 %0, %1, %2, %3;" : "=l"(aB2) : "l"(wreg[2][k]), "l"(qb), "l"(aB2));
            asm("fma.rn.f32x2 %0, %1, %2, %3;" : "=l"(aA3) : "l"(wreg[3][k]), "l"(qa), "l"(aA3));
            asm("fma.rn.f32x2 %0, %1, %2, %3;" : "=l"(aB3) : "l"(wreg[3][k]), "l"(qb), "l"(aB3));
        }

        // collapse to scalars
        float sA0, sA1, sA2, sA3, sB0, sB1, sB2, sB3;
        {
            float lo, hi;
            asm("mov.b64 {%0,%1}, %2;" : "=f"(lo), "=f"(hi) : "l"(aA0)); sA0 = lo + hi;
            asm("mov.b64 {%0,%1}, %2;" : "=f"(lo), "=f"(hi) : "l"(aA1)); sA1 = lo + hi;
            asm("mov.b64 {%0,%1}, %2;" : "=f"(lo), "=f"(hi) : "l"(aA2)); sA2 = lo + hi;
            asm("mov.b64 {%0,%1}, %2;" : "=f"(lo), "=f"(hi) : "l"(aA3)); sA3 = lo + hi;
            asm("mov.b64 {%0,%1}, %2;" : "=f"(lo), "=f"(hi) : "l"(aB0)); sB0 = lo + hi;
            asm("mov.b64 {%0,%1}, %2;" : "=f"(lo), "=f"(hi) : "l"(aB1)); sB1 = lo + hi;
            asm("mov.b64 {%0,%1}, %2;" : "=f"(lo), "=f"(hi) : "l"(aB2)); sB2 = lo + hi;
            asm("mov.b64 {%0,%1}, %2;" : "=f"(lo), "=f"(hi) : "l"(aB3)); sB3 = lo + hi;
        }

        // round 1: xor 8 (A and B interleaved)
        float sendA_A = keep_lo1 ? sA2 : sA0;
        float sendB_A = keep_lo1 ? sA3 : sA1;
        float sendA_B = keep_lo1 ? sB2 : sB0;
        float sendB_B = keep_lo1 ? sB3 : sB1;
        float rcvA_A = __shfl_xor_sync(0xffffffffu, sendA_A, 8);
        float rcvA_B = __shfl_xor_sync(0xffffffffu, sendA_B, 8);
        float rcvB_A = __shfl_xor_sync(0xffffffffu, sendB_A, 8);
        float rcvB_B = __shfl_xor_sync(0xffffffffu, sendB_B, 8);
        float pA0 = (keep_lo1 ? sA0 : sA2) + rcvA_A;
        float pA1 = (keep_lo1 ? sA1 : sA3) + rcvB_A;
        float pB0 = (keep_lo1 ? sB0 : sB2) + rcvA_B;
        float pB1 = (keep_lo1 ? sB1 : sB3) + rcvB_B;

        // round 2: xor 16
        float send2_A = keep_lo2 ? pA1 : pA0;
        float send2_B = keep_lo2 ? pB1 : pB0;
        float rcv2_A = __shfl_xor_sync(0xffffffffu, send2_A, 16);
        float rcv2_B = __shfl_xor_sync(0xffffffffu, send2_B, 16);
        float totA = (keep_lo2 ? pA0 : pA1) + rcv2_A;
        float totB = (keep_lo2 ? pB0 : pB1) + rcv2_B;

        float preA = uA + totA;
        float preB = uB + totB;
        float hnA, hnB;
        asm("tanh.approx.f32 %0, %1;" : "=f"(hnA) : "f"(preA));
        asm("tanh.approx.f32 %0, %1;" : "=f"(hnB) : "f"(preB));
        hA = (t < stepsA) ? hnA : hA;
        hB = (t < stepsB) ? hnB : hB;

        buf ^= 1;
        hsm[w][0][buf][myrow] = hA;
        hsm[w][1][buf][myrow] = hB;
        __syncwarp();
    }

    if (samp0 < B)
        out_h[(size_t)samp0 * HIDDEN + myrow] = hA;
    if (samp0 + 1 < B)
        out_h[(size_t)(samp0 + 1) * HIDDEN + myrow] = hB;
}

// ---------------------------------------------------------------------------
// kernel_launch
// Inputs: glyph_chars, glyph_colors, emb_table, W_ih, W_hh, b_ih, b_hh
// Output: concat(h [B,32], emb [B,64,20], bag [B,64]) float32
// ---------------------------------------------------------------------------
extern "C" void kernel_launch(void* const* d_in, const int* in_sizes, int n_in,
                              void* d_out, int out_size)
{
    const int*   chars  = (const int*)  d_in[0];
    const int*   colors = (const int*)  d_in[1];
    const float* emb    = (const float*)d_in[2];
    const float* W_ih   = (const float*)d_in[3];
    const float* W_hh   = (const float*)d_in[4];
    const float* b_ih   = (const float*)d_in[5];
    const float* b_hh   = (const float*)d_in[6];

    const int B = in_sizes[0] / HW;

    float* out = (float*)d_out;
    const long long nh   = (long long)B * HIDDEN;
    const long long nemb = (long long)B * MAX_LEN * EMB_DIM;

    float* out_h   = out;
    float* out_emb = out + nh;
    float* out_bag = out + nh + nemb;

    int blocks = (B + SPW * WPB - 1) / (SPW * WPB);
    if (blocks < NPROD) blocks = NPROD;
    mega_kernel<<<blocks, WPB * 32>>>(chars, colors, emb, W_ih, W_hh,
                                      b_ih, b_hh, out_h, out_emb, out_bag, B);
}

// round 17
// speedup vs baseline: 1.0676x; 1.0676x over previous
#include <cuda_runtime.h>
#include <cuda_bf16.h>
#include <cstdint>

#define GLYPH_DIM 4096
#define PAD_IDX   4096
#define EMB_DIM   20
#define HIDDEN    32
#define MAX_LEN   64
#define HW        1659        // 21 * 79
#define WPB       4           // warps per block
#define SPW       2           // samples per warp
#define WIN       1024        // presence window size
#define NPROD     256         // producer blocks for utab

typedef unsigned long long ull;

// ---------------------------------------------------------------------------
// Device scratch
// ---------------------------------------------------------------------------
__device__ float g_utab[(GLYPH_DIM + 1) * HIDDEN];
__device__ ull   g_done;      // monotonic producer counter (zero at module load)

// ---------------------------------------------------------------------------
// Mega kernel
// ---------------------------------------------------------------------------
__global__ __launch_bounds__(WPB * 32, 8) void mega_kernel(
    const int* __restrict__ chars,
    const int* __restrict__ colors,
    const float* __restrict__ emb,
    const float* __restrict__ W_ih,
    const float* __restrict__ W_hh,
    const float* __restrict__ b_ih,
    const float* __restrict__ b_hh,
    float* __restrict__ out_h,
    float* __restrict__ out_emb,
    float* __restrict__ out_bag,
    int B)
{
    __shared__ __align__(16) unsigned char presence[WPB][WIN];       // 4 KB
    __shared__ __align__(16) int   bagsh[WPB][SPW][MAX_LEN + 4];
    __shared__ __align__(16) float hsm  [WPB][SPW][2][HIDDEN];

    const int lane = threadIdx.x & 31;
    const int w    = threadIdx.x >> 5;

    // ---- utab producer prologue (blocks 0..NPROD-1) ----
    if (blockIdx.x < NPROD) {
        const int uw = blockIdx.x * WPB + w;          // 0..1023
        const float4* wr = (const float4*)(W_ih + lane * EMB_DIM);
        float4 w0 = __ldg(&wr[0]), w1 = __ldg(&wr[1]), w2 = __ldg(&wr[2]),
               w3 = __ldg(&wr[3]), w4 = __ldg(&wr[4]);
        float bias = __ldg(&b_ih[lane]) + __ldg(&b_hh[lane]);
        for (int row = uw; row <= GLYPH_DIM; row += NPROD * WPB) {
            const float4* er = (const float4*)(emb + (size_t)row * EMB_DIM);
            float4 e0 = __ldg(&er[0]), e1 = __ldg(&er[1]), e2 = __ldg(&er[2]),
                   e3 = __ldg(&er[3]), e4 = __ldg(&er[4]);
            float acc = bias;
            acc += w0.x*e0.x + w0.y*e0.y + w0.z*e0.z + w0.w*e0.w;
            acc += w1.x*e1.x + w1.y*e1.y + w1.z*e1.z + w1.w*e1.w;
            acc += w2.x*e2.x + w2.y*e2.y + w2.z*e2.z + w2.w*e2.w;
            acc += w3.x*e3.x + w3.y*e3.y + w3.z*e3.z + w3.w*e3.w;
            acc += w4.x*e4.x + w4.y*e4.y + w4.z*e4.z + w4.w*e4.w;
            g_utab[row * HIDDEN + lane] = acc;
        }
        __syncthreads();
        if (threadIdx.x == 0) {
            __threadfence();
            atomicAdd(&g_done, 1ull);
        }
    }

    const int gw = blockIdx.x * WPB + w;              // global warp id
    const int samp0 = gw * SPW;
    if (samp0 >= B) return;

    int steps_arr[SPW];

    // ---- bag construction + outputs, per sample (sequential) ----
    for (int s = 0; s < SPW; s++) {
        const int sample = samp0 + s;
        if (sample >= B) {
            steps_arr[s] = 0;
#pragma unroll
            for (int i = lane; i < MAX_LEN; i += 32) bagsh[w][s][i] = PAD_IDX;
            __syncwarp();
            continue;
        }

        const size_t base = (size_t)sample * HW;
        const int* cp = chars + base;
        const int* kp = colors + base;
        const int mis = (int)(base & 3);
        const int pre = (4 - mis) & 3;
        const int nv  = (HW - pre) >> 2;
        const int rem = HW - pre - (nv << 2);
        const int4* cp4 = (const int4*)(cp + pre);
        const int4* kp4 = (const int4*)(kp + pre);

        int o_acc = 0;
        for (int wnd = 0; wnd < GLYPH_DIM / WIN; wnd++) {
            const int wb = wnd << 10;

            {
                uint4 z = make_uint4(0u, 0u, 0u, 0u);
                uint4* p4 = (uint4*)presence[w];
                p4[lane] = z;
                p4[lane + 32] = z;
            }
            __syncwarp();

            if (lane < pre) {
                unsigned rel = (unsigned)((__ldg(&cp[lane]) << 4) + __ldg(&kp[lane]) - wb);
                if (rel < WIN) presence[w][rel] = 1;
            }
#pragma unroll 4
            for (int i = lane; i < nv; i += 32) {
                int4 c = __ldg(&cp4[i]);
                int4 k = __ldg(&kp4[i]);
                unsigned r0 = (unsigned)((c.x << 4) + k.x - wb);
                unsigned r1 = (unsigned)((c.y << 4) + k.y - wb);
                unsigned r2 = (unsigned)((c.z << 4) + k.z - wb);
                unsigned r3 = (unsigned)((c.w << 4) + k.w - wb);
                if (r0 < WIN) presence[w][r0] = 1;
                if (r1 < WIN) presence[w][r1] = 1;
                if (r2 < WIN) presence[w][r2] = 1;
                if (r3 < WIN) presence[w][r3] = 1;
            }
            if (lane < rem) {
                int idx = pre + (nv << 2) + lane;
                unsigned rel = (unsigned)((__ldg(&cp[idx]) << 4) + __ldg(&kp[idx]) - wb);
                if (rel < WIN) presence[w][rel] = 1;
            }
            __syncwarp();

            unsigned combined;
            {
                const uint4* pq = (const uint4*)presence[w];
                uint4 A  = pq[lane];
                uint4 Bv = pq[lane + 32];
                unsigned lo = (((A.x  * 0x01020408u) >> 24) & 0xFu)
                            | ((((A.y  * 0x01020408u) >> 24) & 0xFu) << 4)
                            | ((((A.z  * 0x01020408u) >> 24) & 0xFu) << 8)
                            | ((((A.w  * 0x01020408u) >> 24) & 0xFu) << 12);
                unsigned hi = (((Bv.x * 0x01020408u) >> 24) & 0xFu)
                            | ((((Bv.y * 0x01020408u) >> 24) & 0xFu) << 4)
                            | ((((Bv.z * 0x01020408u) >> 24) & 0xFu) << 8)
                            | ((((Bv.w * 0x01020408u) >> 24) & 0xFu) << 12);
                combined = lo | (hi << 16);
            }
            unsigned v0 = __shfl_sync(0xffffffffu, combined, (2 * lane) & 31);
            unsigned v1 = __shfl_sync(0xffffffffu, combined, (2 * lane + 1) & 31);
            if (lane >= 16) { v0 >>= 16; v1 >>= 16; }
            unsigned word = (v0 & 0xFFFFu) | ((v1 & 0xFFFFu) << 16);

            int cnt = __popc(word);
            int incl = cnt;
#pragma unroll
            for (int d = 1; d < 32; d <<= 1) {
                int n = __shfl_up_sync(0xffffffffu, incl, d);
                if (lane >= d) incl += n;
            }
            int wtotal = __shfl_sync(0xffffffffu, incl, 31);
            int o = o_acc + incl - cnt;

            unsigned mm = word;
            int idbase = wb + 32 * lane;
            while (mm && o < MAX_LEN) {
                int b = __ffs(mm) - 1;
                bagsh[w][s][o++] = idbase + b;
                mm &= mm - 1;
            }
            o_acc += wtotal;
            __syncwarp();
            if (o_acc >= MAX_LEN) break;
        }

        steps_arr[s] = o_acc < MAX_LEN ? o_acc : MAX_LEN;
#pragma unroll
        for (int i = lane; i < MAX_LEN; i += 32)
            if (i >= o_acc) bagsh[w][s][i] = PAD_IDX;
        __syncwarp();

        // bag output
        if (lane < 16) {
            int4 bi = ((const int4*)bagsh[w][s])[lane];
            float4 bf;
            bf.x = (float)bi.x; bf.y = (float)bi.y;
            bf.z = (float)bi.z; bf.w = (float)bi.w;
            ((float4*)(out_bag + (size_t)sample * MAX_LEN))[lane] = bf;
        }
        // emb gather
        {
            float4* dst4 = (float4*)(out_emb + (size_t)sample * (MAX_LEN * EMB_DIM));
            const float4* esrc = (const float4*)emb;
#pragma unroll
            for (int it = 0; it < 10; it++) {
                int e4 = it * 32 + lane;
                int r  = e4 / 5;
                int k  = e4 - r * 5;
                int g  = bagsh[w][s][r];
                dst4[e4] = __ldg(&esrc[(size_t)g * 5 + k]);
            }
        }
    }

    // ---- wait for utab ----
    if (lane == 0) {
        volatile ull* dp = &g_done;
        while (*dp < (ull)NPROD) { __nanosleep(64); }
    }
    __syncwarp();
    __threadfence();

    // ---- RNN: quarter-j split, scalar-collapse, TWO samples interleaved ----
    const int jq = lane >> 3;
    const int p  = lane & 7;
    const int myrow = 4 * p + 2 * (jq & 1) + (jq >> 1);
    const bool keep_lo1 = (jq & 1) == 0;
    const bool keep_lo2 = (jq >> 1) == 0;

    ull wreg[4][4];                      // shared across both samples
    {
#pragma unroll
        for (int r = 0; r < 4; r++) {
            const ull* wp = (const ull*)(W_hh + (4 * p + r) * HIDDEN + 8 * jq);
#pragma unroll
            for (int k = 0; k < 4; k++) wreg[r][k] = __ldg(&wp[k]);
        }
    }

    int idA0 = bagsh[w][0][lane];
    int idA1 = bagsh[w][0][32 + lane];
    int idB0 = bagsh[w][1][lane];
    int idB1 = bagsh[w][1][32 + lane];
    const int stepsA = steps_arr[0];
    const int stepsB = steps_arr[1];

    hsm[w][0][0][lane] = 0.f;
    hsm[w][1][0][lane] = 0.f;
    float hA = 0.f, hB = 0.f;
    int buf = 0;
    __syncwarp();

    float uringA[4], uringB[4];
#pragma unroll
    for (int k = 0; k < 4; k++) {
        int gA = __shfl_sync(0xffffffffu, idA0, k);
        int gB = __shfl_sync(0xffffffffu, idB0, k);
        uringA[k] = __ldg(&g_utab[gA * HIDDEN + myrow]);
        uringB[k] = __ldg(&g_utab[gB * HIDDEN + myrow]);
    }

#pragma unroll 2
    for (int t = 0; t < MAX_LEN; t++) {
        float uA = uringA[t & 3];
        float uB = uringB[t & 3];
        {
            int tn = t + 4;
            if (tn > MAX_LEN - 1) tn = MAX_LEN - 1;
            int gA = __shfl_sync(0xffffffffu, (tn < 32) ? idA0 : idA1, tn & 31);
            int gB = __shfl_sync(0xffffffffu, (tn < 32) ? idB0 : idB1, tn & 31);
            uringA[t & 3] = __ldg(&g_utab[gA * HIDDEN + myrow]);
            uringB[t & 3] = __ldg(&g_utab[gB * HIDDEN + myrow]);
        }

        const ulonglong2* hpA = (const ulonglong2*)&hsm[w][0][buf][8 * jq];
        const ulonglong2* hpB = (const ulonglong2*)&hsm[w][1][buf][8 * jq];
        ulonglong2 qA0 = hpA[0];
        ulonglong2 qA1 = hpA[1];
        ulonglong2 qB0 = hpB[0];
        ulonglong2 qB1 = hpB[1];

        ull aA0 = 0ull, aA1 = 0ull, aA2 = 0ull, aA3 = 0ull;
        ull aB0 = 0ull, aB1 = 0ull, aB2 = 0ull, aB3 = 0ull;
#pragma unroll
        for (int k = 0; k < 4; k++) {
            ull qa = (k == 0) ? qA0.x : (k == 1) ? qA0.y : (k == 2) ? qA1.x : qA1.y;
            ull qb = (k == 0) ? qB0.x : (k == 1) ? qB0.y : (k == 2) ? qB1.x : qB1.y;
            asm("fma.rn.f32x2 %0, %1, %2, %3;" : "=l"(aA0) : "l"(wreg[0][k]), "l"(qa), "l"(aA0));
            asm("fma.rn.f32x2 %0, %1, %2, %3;" : "=l"(aB0) : "l"(wreg[0][k]), "l"(qb), "l"(aB0));
            asm("fma.rn.f32x2 %0, %1, %2, %3;" : "=l"(aA1) : "l"(wreg[1][k]), "l"(qa), "l"(aA1));
            asm("fma.rn.f32x2 %0, %1, %2, %3;" : "=l"(aB1) : "l"(wreg[1][k]), "l"(qb), "l"(aB1));
            asm("fma.rn.f32x2 %0, %1, %2, %3;" : "=l"(aA2) : "l"(wreg[2][k]), "l"(qa), "l"(aA2));
            asm("fma.rn.f32x2 %0, %1, %2, %3;" : "=l"(aB2) : "l"(wreg[2][k]), "l"(qb), "l"(aB2));
            asm("fma.rn.f32x2 %0, %1, %2, %3;" : "=l"(aA3) : "l"(wreg[3][k]), "l"(qa), "l"(aA3));
            asm("fma.rn.f32x2 %0, %1, %2, %3;" : "=l"(aB3) : "l"(wreg[3][k]), "l"(qb), "l"(aB3));
        }

        // collapse to scalars
        float sA0, sA1, sA2, sA3, sB0, sB1, sB2, sB3;
        {
            float lo, hi;
            asm("mov.b64 {%0,%1}, %2;" : "=f"(lo), "=f"(hi) : "l"(aA0)); sA0 = lo + hi;
            asm("mov.b64 {%0,%1}, %2;" : "=f"(lo), "=f"(hi) : "l"(aA1)); sA1 = lo + hi;
            asm("mov.b64 {%0,%1}, %2;" : "=f"(lo), "=f"(hi) : "l"(aA2)); sA2 = lo + hi;
            asm("mov.b64 {%0,%1}, %2;" : "=f"(lo), "=f"(hi) : "l"(aA3)); sA3 = lo + hi;
            asm("mov.b64 {%0,%1}, %2;" : "=f"(lo), "=f"(hi) : "l"(aB0)); sB0 = lo + hi;
            asm("mov.b64 {%0,%1}, %2;" : "=f"(lo), "=f"(hi) : "l"(aB1)); sB1 = lo + hi;
            asm("mov.b64 {%0,%1}, %2;" : "=f"(lo), "=f"(hi) : "l"(aB2)); sB2 = lo + hi;
            asm("mov.b64 {%0,%1}, %2;" : "=f"(lo), "=f"(hi) : "l"(aB3)); sB3 = lo + hi;
        }

        // round 1: xor 8 (A and B interleaved)
        float sendA_A = keep_lo1 ? sA2 : sA0;
        float sendB_A = keep_lo1 ? sA3 : sA1;
        float sendA_B = keep_lo1 ? sB2 : sB0;
        float sendB_B = keep_lo1 ? sB3 : sB1;
        float rcvA_A = __shfl_xor_sync(0xffffffffu, sendA_A, 8);
        float rcvA_B = __shfl_xor_sync(0xffffffffu, sendA_B, 8);
        float rcvB_A = __shfl_xor_sync(0xffffffffu, sendB_A, 8);
        float rcvB_B = __shfl_xor_sync(0xffffffffu, sendB_B, 8);
        float pA0 = (keep_lo1 ? sA0 : sA2) + rcvA_A;
        float pA1 = (keep_lo1 ? sA1 : sA3) + rcvB_A;
        float pB0 = (keep_lo1 ? sB0 : sB2) + rcvA_B;
        float pB1 = (keep_lo1 ? sB1 : sB3) + rcvB_B;

        // round 2: xor 16
        float send2_A = keep_lo2 ? pA1 : pA0;
        float send2_B = keep_lo2 ? pB1 : pB0;
        float rcv2_A = __shfl_xor_sync(0xffffffffu, send2_A, 16);
        float rcv2_B = __shfl_xor_sync(0xffffffffu, send2_B, 16);
        float totA = (keep_lo2 ? pA0 : pA1) + rcv2_A;
        float totB = (keep_lo2 ? pB0 : pB1) + rcv2_B;

        float preA = uA + totA;
        float preB = uB + totB;
        float hnA, hnB;
        asm("tanh.approx.f32 %0, %1;" : "=f"(hnA) : "f"(preA));
        asm("tanh.approx.f32 %0, %1;" : "=f"(hnB) : "f"(preB));
        hA = (t < stepsA) ? hnA : hA;
        hB = (t < stepsB) ? hnB : hB;

        buf ^= 1;
        hsm[w][0][buf][myrow] = hA;
        hsm[w][1][buf][myrow] = hB;
        __syncwarp();
    }

    if (samp0 < B)
        out_h[(size_t)samp0 * HIDDEN + myrow] = hA;
    if (samp0 + 1 < B)
        out_h[(size_t)(samp0 + 1) * HIDDEN + myrow] = hB;
}

// ---------------------------------------------------------------------------
// kernel_launch
// Inputs: glyph_chars, glyph_colors, emb_table, W_ih, W_hh, b_ih, b_hh
// Output: concat(h [B,32], emb [B,64,20], bag [B,64]) float32
// ---------------------------------------------------------------------------
extern "C" void kernel_launch(void* const* d_in, const int* in_sizes, int n_in,
                              void* d_out, int out_size)
{
    const int*   chars  = (const int*)  d_in[0];
    const int*   colors = (const int*)  d_in[1];
    const float* emb    = (const float*)d_in[2];
    const float* W_ih   = (const float*)d_in[3];
    const float* W_hh   = (const float*)d_in[4];
    const float* b_ih   = (const float*)d_in[5];
    const float* b_hh   = (const float*)d_in[6];

    const int B = in_sizes[0] / HW;

    float* out = (float*)d_out;
    const long long nh   = (long long)B * HIDDEN;
    const long long nemb = (long long)B * MAX_LEN * EMB_DIM;

    float* out_h   = out;
    float* out_emb = out + nh;
    float* out_bag = out + nh + nemb;

    int blocks = (B + SPW * WPB - 1) / (SPW * WPB);
    if (blocks < NPROD) blocks = NPROD;
    mega_kernel<<<blocks, WPB * 32>>>(chars, colors, emb, W_ih, W_hh,
                                      b_ih, b_hh, out_h, out_emb, out_bag, B);
}